// round 16
// baseline (speedup 1.0000x reference)
#include <cuda_runtime.h>
#include <cuda_fp16.h>

#define XD 256
#define HD 2048
#define YD 256
#define TT 4096
#define GRID 128
#define NTH 288          // 8 compute warps + 1 sync warp
#define COLS 16          // hidden columns per CTA per matrix (128*16 = 2048)
#define NUNIT (GRID * 8) // 1024 exchange units (one per compute warp, 2 cols each)

// smem layout:
//   [0, 196608)      packed weights: 3 matrices x 8 col-pairs x 512 int4
//   [196608, +16KB)  y-weights: 2 cols x 512 float4 (rows 128k+4l..+3)
//   [+16KB, +4KB)    hB  staged h  (fp16, row order)
//   [+4KB,  +4KB)    hrB staged hr (fp16, row order)
#define W_BYTES  (3 * 8 * 512 * 16)
#define WY_OFF   W_BYTES
#define HB_OFF   (W_BYTES + 2 * HD * 4)
#define SMEM_SEQ (HB_OFF + HD * 2 + HD * 2)

// ------------------------------------------------------------------
// Device-global scratch (no cudaMalloc allowed)
// ------------------------------------------------------------------
__device__ float g_pre[(size_t)TT * 3 * HD];          // [t][m][j], m: 0=u,1=r,2=c
__device__ __align__(128) unsigned g_hrT[NUNIT];      // hr tags (generation)
__device__ __align__(128) unsigned g_hrD[NUNIT];      // hr data (half2)
__device__ __align__(128) unsigned g_hT[NUNIT];       // h tags
__device__ __align__(128) unsigned g_hD[NUNIT];       // h data (half2)

// ------------------------------------------------------------------
// Init: zero tags (0 < any generation >= 1)
// ------------------------------------------------------------------
__global__ void init_kernel() {
    int i = blockIdx.x * blockDim.x + threadIdx.x;
    if (i < NUNIT) { g_hrT[i] = 0u; g_hT[i] = 0u; }
}

// ------------------------------------------------------------------
// Precompute: g_pre[t, m, j] = x[t] @ Wm[0:256, :] + bm   (parallel GEMM)
// ------------------------------------------------------------------
__global__ void __launch_bounds__(256) pre_gemm(
    const float* __restrict__ x,
    const float* __restrict__ Wu, const float* __restrict__ Wr, const float* __restrict__ Wc,
    const float* __restrict__ bu, const float* __restrict__ br, const float* __restrict__ bc)
{
    const int z = blockIdx.z;
    const float* __restrict__ W    = (z == 0) ? Wu : ((z == 1) ? Wr : Wc);
    const float* __restrict__ bias = (z == 0) ? bu : ((z == 1) ? br : bc);

    __shared__ __align__(16) float As[64][16];
    __shared__ __align__(16) float Bs[16][64];

    const int tid = threadIdx.x;
    const int tx = tid & 15;
    const int ty = tid >> 4;
    const int row0 = blockIdx.y * 64;
    const int col0 = blockIdx.x * 64;

    float acc[4][4];
#pragma unroll
    for (int i = 0; i < 4; i++)
#pragma unroll
        for (int j = 0; j < 4; j++) acc[i][j] = 0.f;

    for (int k0 = 0; k0 < XD; k0 += 16) {
#pragma unroll
        for (int l = 0; l < 4; l++) {
            int idx = tid + l * 256;
            int kk = idx & 15, r = idx >> 4;
            As[r][kk] = x[(size_t)(row0 + r) * XD + k0 + kk];
        }
#pragma unroll
        for (int l = 0; l < 4; l++) {
            int idx = tid + l * 256;
            int c = idx & 63, kk = idx >> 6;
            Bs[kk][c] = W[(size_t)(k0 + kk) * HD + col0 + c];
        }
        __syncthreads();
#pragma unroll
        for (int kk = 0; kk < 16; kk++) {
            float a[4];
#pragma unroll
            for (int i = 0; i < 4; i++) a[i] = As[ty * 4 + i][kk];
            float4 b4 = ((const float4*)&Bs[kk][0])[tx];
            float b[4] = {b4.x, b4.y, b4.z, b4.w};
#pragma unroll
            for (int i = 0; i < 4; i++)
#pragma unroll
                for (int j = 0; j < 4; j++)
                    acc[i][j] = fmaf(a[i], b[j], acc[i][j]);
        }
        __syncthreads();
    }

#pragma unroll
    for (int i = 0; i < 4; i++) {
        int t = row0 + ty * 4 + i;
#pragma unroll
        for (int j = 0; j < 4; j++) {
            int c = col0 + tx * 4 + j;
            g_pre[(size_t)t * (3 * HD) + (size_t)z * HD + c] = acc[i][j] + bias[c];
        }
    }
}

// ------------------------------------------------------------------
// Helpers
// ------------------------------------------------------------------
#define BAR_SYNC(id)   asm volatile("bar.sync %0, %1;"   :: "r"(id), "r"(NTH) : "memory")
#define BAR_ARRIVE(id) asm volatile("bar.arrive %0, %1;" :: "r"(id), "r"(NTH) : "memory")

__device__ __forceinline__ float warp_sum(float v) {
#pragma unroll
    for (int o = 16; o; o >>= 1) v += __shfl_xor_sync(0xffffffffu, v, o);
    return v;
}

__device__ __forceinline__ float fsig(float x)   { return 1.f / (1.f + __expf(-x)); }
__device__ __forceinline__ float ftanh_(float x) { return 2.f / (1.f + __expf(-2.f * x)) - 1.f; }

// Morally-strong message passing (PTX memory model guarantees atomicity+order)
__device__ __forceinline__ void st_rlx(unsigned* p, unsigned v) {
    asm volatile("st.relaxed.gpu.global.b32 [%0], %1;" :: "l"(p), "r"(v) : "memory");
}
__device__ __forceinline__ void st_rel(unsigned* p, unsigned v) {
    asm volatile("st.release.gpu.global.b32 [%0], %1;" :: "l"(p), "r"(v) : "memory");
}
__device__ __forceinline__ unsigned ld_acq(const unsigned* p) {
    unsigned v;
    asm volatile("ld.acquire.gpu.global.b32 %0, [%1];" : "=r"(v) : "l"(p) : "memory");
    return v;
}
__device__ __forceinline__ unsigned ld_rlx(const unsigned* p) {
    unsigned v;
    asm volatile("ld.relaxed.gpu.global.b32 %0, [%1];" : "=r"(v) : "l"(p) : "memory");
    return v;
}

// Two 2048-long dots: packed int4 weights (LDS.128: 4 rows x 2 cols) x fp32 h.
__device__ __forceinline__ void dot2_q(const int4* __restrict__ wp,
                                       const float2* hreg, int lane,
                                       float& r0, float& r1) {
    float a0 = 0.f, a1 = 0.f, b0 = 0.f, b1 = 0.f;
#pragma unroll
    for (int k = 0; k < 16; k++) {
        int4 wv = wp[k * 32 + lane];
        float2 h01 = hreg[2 * k], h23 = hreg[2 * k + 1];
        float2 xa = __half22float2(*(__half2*)&wv.x);
        float2 xb = __half22float2(*(__half2*)&wv.y);
        float2 xc = __half22float2(*(__half2*)&wv.z);
        float2 xd = __half22float2(*(__half2*)&wv.w);
        a0 = fmaf(xa.x, h01.x, a0); a1 = fmaf(xa.y, h01.y, a1);
        a0 = fmaf(xb.x, h23.x, a0); a1 = fmaf(xb.y, h23.y, a1);
        b0 = fmaf(xc.x, h01.x, b0); b1 = fmaf(xc.y, h01.y, b1);
        b0 = fmaf(xd.x, h23.x, b0); b1 = fmaf(xd.y, h23.y, b1);
    }
    r0 = warp_sum(a0 + a1);
    r1 = warp_sum(b0 + b1);
}

__device__ __forceinline__ float dot_y4(const float4* __restrict__ wy4,
                                        const float2* hreg, int lane) {
    float a0 = 0.f, a1 = 0.f;
#pragma unroll
    for (int k = 0; k < 16; k++) {
        float4 wv = wy4[k * 32 + lane];
        float2 h01 = hreg[2 * k], h23 = hreg[2 * k + 1];
        a0 = fmaf(wv.x, h01.x, a0); a1 = fmaf(wv.y, h01.y, a1);
        a0 = fmaf(wv.z, h23.x, a0); a1 = fmaf(wv.w, h23.y, a1);
    }
    return warp_sum(a0 + a1);
}

// Load staged fp16 vector (smem, row order) into fp32 registers, packed row
// mapping: hreg[2k],hreg[2k+1] = rows 128k+4*lane .. +3.
__device__ __forceinline__ void load_hreg(const __half* buf, int lane, float2* hreg) {
#pragma unroll
    for (int k = 0; k < 16; k++) {
        uint2 v = ((const uint2*)buf)[k * 32 + lane];
        hreg[2 * k]     = __half22float2(*(__half2*)&v.x);
        hreg[2 * k + 1] = __half22float2(*(__half2*)&v.y);
    }
}

// Sync-warp sweep: each lane owns units [lane*32, lane*32+32). For each unit,
// acquire-poll its tag until == gen, then relaxed-load its data and STS.
// Tag lines: one 128B line per lane, polled by 1 lane per CTA (128 streams/line
// chip-wide — the R9-proven-safe density). Pending-mask loop keeps independent
// loads in flight.
__device__ __forceinline__ void ll_sweep(const unsigned* __restrict__ tags,
                                         const unsigned* __restrict__ data,
                                         __half* dstS, int lane, unsigned gen) {
    const int base = lane * 32;
    unsigned pend = 0xffffffffu;
    while (pend) {
        unsigned m = pend;
        while (m) {
            int i = __ffs(m) - 1;
            m &= m - 1;
            if (ld_acq(tags + base + i) == gen) {
                ((unsigned*)dstS)[base + i] = ld_rlx(data + base + i);
                pend &= ~(1u << i);
            }
        }
    }
}

// ------------------------------------------------------------------
// Persistent sequential kernel: 128 co-resident CTAs (1/SM).
// Warps 0-7 compute + release-publish; warp 8 acquire-sweeps into smem.
// Two block barriers per step, zero fences, zero global atomics.
// ------------------------------------------------------------------
__global__ void __launch_bounds__(NTH, 1) gru_seq(
    const float* __restrict__ h0,
    const float* __restrict__ Wu, const float* __restrict__ Wr, const float* __restrict__ Wc,
    const float* __restrict__ Why, const float* __restrict__ by,
    float* __restrict__ out, int out_size)
{
    extern __shared__ char sm[];
    int4*   wP  = (int4*)sm;                    // packed weights
    float*  wyS = (float*)(sm + WY_OFF);        // y cols as float4 tiles
    __half* hB  = (__half*)(sm + HB_OFF);       // staged h  (fp16)
    __half* hrB = hB + HD;                      // staged hr (fp16)

    const int tid  = threadIdx.x;
    const int lane = tid & 31;
    const int w    = tid >> 5;         // 0..8
    const bool comp = (w < 8);
    const int cta  = blockIdx.x;
    const int colBase = cta * COLS;
    const int unit = cta * 8 + (comp ? w : 0);  // this warp's exchange unit

    // ---- one-time: pack h-part weights into per-warp int4 tiles ----
#pragma unroll 1
    for (int m = 0; m < 3; m++) {
        const float* __restrict__ Wm =
            ((m == 0) ? Wu : ((m == 1) ? Wr : Wc)) + (size_t)XD * HD;  // skip x rows
        for (int idx = tid; idx < COLS * HD; idx += NTH) {
            int cl  = idx & (COLS - 1);
            int row = idx >> 4;
            int p = cl >> 1, sub = cl & 1;
            int k = row >> 7, ln = (row >> 2) & 31, q = row & 3;
            __half* dst = (__half*)(wP + ((m * 8 + p) * 512 + k * 32 + ln));
            dst[sub * 4 + q] = __float2half_rn(Wm[(size_t)row * HD + colBase + cl]);
        }
    }
    // y columns (float4 tiles): global y cols {2*cta, 2*cta+1}
    for (int idx = tid; idx < 2 * HD; idx += NTH) {
        int c = idx & 1, row = idx >> 1;
        int k = row >> 7, ln = (row >> 2) & 31, q = row & 3;
        wyS[c * HD + (k * 32 + ln) * 4 + q] = Why[(size_t)row * YD + cta * 2 + c];
    }
    // initial h staged as fp16 (row order) into hB
    for (int idx = tid; idx < HD; idx += NTH)
        hB[idx] = __float2half_rn(h0[idx]);

    const int j0 = colBase + (comp ? 2 * w : 0), j1 = j0 + 1;
    const int4* wpU = wP + (size_t)(0 * 8 + (comp ? w : 0)) * 512;
    const int4* wpR = wP + (size_t)(1 * 8 + (comp ? w : 0)) * 512;
    const int4* wpC = wP + (size_t)(2 * 8 + (comp ? w : 0)) * 512;
    const float4* wy4 = (const float4*)(wyS + (w < 2 ? w : 0) * HD);
    const float   yb  = (w < 2) ? by[cta * 2 + w] : 0.f;

    // own-column state kept exact in fp32 registers across steps
    float hold0 = 0.f, hold1 = 0.f;
    float2 pu = make_float2(0.f, 0.f), pr = pu, pc = pu;
    if (comp) {
        hold0 = h0[j0]; hold1 = h0[j1];
        pu = __ldcg((const float2*)&g_pre[0 * HD + j0]);
        pr = __ldcg((const float2*)&g_pre[1 * HD + j0]);
        pc = __ldcg((const float2*)&g_pre[2 * HD + j0]);
    }
    __syncthreads();

    float2 hreg[32];

    for (int t = 0; t < TT; t++) {
        const unsigned gen = (unsigned)(t + 1);
        if (comp) {
            // hB holds h_t (fp16) -> registers fp32
            load_hreg(hB, lane, hreg);

            // ---- reset gate, release-publish h*Lr ----
            float r0, r1;
            dot2_q(wpR, hreg, lane, r0, r1);
            r0 = fsig(r0 + pr.x);
            r1 = fsig(r1 + pr.y);
            if (lane == 0) {
                __half2 hv = __floats2half2_rn(hold0 * r0, hold1 * r1);
                st_rlx(&g_hrD[unit], *(unsigned*)&hv);   // data first (relaxed)
                st_rel(&g_hrT[unit], gen);               // tag second (release)
            }

            // ---- exchange shadow: update gate + y[t-1] ----
            float u0, u1;
            dot2_q(wpU, hreg, lane, u0, u1);
            u0 = fsig(u0 + pu.x);
            u1 = fsig(u1 + pu.y);
            if (w < 2 && t > 0) {
                float yv = dot_y4(wy4, hreg, lane) + yb;
                if (lane == 0) out[(size_t)(t - 1) * YD + cta * 2 + w] = yv;
            }
            BAR_SYNC(2);                        // wait: hr swept into hrB

            // ---- candidate + new h (hreg reused for hr) ----
            load_hreg(hrB, lane, hreg);
            float cc0, cc1;
            dot2_q(wpC, hreg, lane, cc0, cc1);
            cc0 = ftanh_(cc0 + pc.x);
            cc1 = ftanh_(cc1 + pc.y);
            const float hn0 = cc0 * u0 + hold0 * (1.f - u0);
            const float hn1 = cc1 * u1 + hold1 * (1.f - u1);
            hold0 = hn0; hold1 = hn1;           // exact fp32 carry
            if (lane == 0) {
                __half2 hv = __floats2half2_rn(hn0, hn1);
                st_rlx(&g_hD[unit], *(unsigned*)&hv);
                st_rel(&g_hT[unit], gen);
            }

            // ---- exchange shadow: prefetch pre[t+1] ----
            if (t + 1 < TT) {
                const float* pn = g_pre + (size_t)(t + 1) * (3 * HD);
                pu = __ldcg((const float2*)&pn[0 * HD + j0]);
                pr = __ldcg((const float2*)&pn[1 * HD + j0]);
                pc = __ldcg((const float2*)&pn[2 * HD + j0]);
            }
            BAR_SYNC(4);                        // wait: h_{t+1} swept into hB
        } else {
            // ================= sync warp: acquire sweeps =================
            ll_sweep(g_hrT, g_hrD, hrB, lane, gen);   // concurrent with r/u compute
            BAR_ARRIVE(2);                            // hrB ready
            ll_sweep(g_hT, g_hD, hB, lane, gen);      // concurrent with candidate
            BAR_ARRIVE(4);                            // hB ready
        }
    }

    // ---- epilogue: hB = h_TT ----
    if (w < 2) {
        load_hreg(hB, lane, hreg);
        float yv = dot_y4(wy4, hreg, lane) + yb;
        if (lane == 0) out[(size_t)(TT - 1) * YD + cta * 2 + w] = yv;
    }
    // h_fin: exact fp32 own-column state
    if (comp && lane == 0 && out_size >= TT * YD + HD) {
        out[(size_t)TT * YD + j0] = hold0;
        out[(size_t)TT * YD + j1] = hold1;
    }
}

// ------------------------------------------------------------------
// Launch
// ------------------------------------------------------------------
extern "C" void kernel_launch(void* const* d_in, const int* in_sizes, int n_in,
                              void* d_out, int out_size) {
    const float* x   = (const float*)d_in[0];
    const float* h0  = (const float*)d_in[1];
    const float* Wc  = (const float*)d_in[2];
    const float* Wu  = (const float*)d_in[3];
    const float* Wr  = (const float*)d_in[4];
    const float* bc  = (const float*)d_in[5];
    const float* bu  = (const float*)d_in[6];
    const float* br  = (const float*)d_in[7];
    const float* Why = (const float*)d_in[8];
    const float* by  = (const float*)d_in[9];
    float* out = (float*)d_out;

    cudaFuncSetAttribute(gru_seq, cudaFuncAttributeMaxDynamicSharedMemorySize, SMEM_SEQ);

    init_kernel<<<4, 256>>>();

    dim3 g(HD / 64, TT / 64, 3);
    pre_gemm<<<g, 256>>>(x, Wu, Wr, Wc, bu, br, bc);

    gru_seq<<<GRID, NTH, SMEM_SEQ>>>(h0, Wu, Wr, Wc, Why, by, out, out_size);
}

// round 17
// speedup vs baseline: 7.7541x; 7.7541x over previous
#include <cuda_runtime.h>
#include <cuda_fp16.h>

#define XD 256
#define HD 2048
#define YD 256
#define TT 4096
#define GRID 128
#define NTH 288          // 8 compute warps + 1 sync warp
#define COLS 16          // hidden columns per CTA per matrix (128*16 = 2048)

// smem layout:
//   [0, 196608)      packed weights: 3 matrices x 8 col-pairs x 512 int4
//                    int4[(m*8+p)*512 + k*32+lane] = 4 rows x 2 cols fp16
//   [196608, +16KB)  y-weights: 2 cols x 512 float4 (rows 128k+4l..+3)
//   [+16KB, +4KB)    hB  staged h  (fp16, row order)
//   [+4KB,  +4KB)    hrB staged hr (fp16, row order)
#define W_BYTES  (3 * 8 * 512 * 16)
#define WY_OFF   W_BYTES
#define HB_OFF   (W_BYTES + 2 * HD * 4)
#define SMEM_SEQ (HB_OFF + HD * 2 + HD * 2)

// ------------------------------------------------------------------
// Device-global scratch (no cudaMalloc allowed)
// ------------------------------------------------------------------
__device__ float g_pre[(size_t)TT * 3 * HD];      // [t][m][j], m: 0=u,1=r,2=c (x-part + bias)
__device__ __align__(16) __half g_h2[HD];         // published h (fp16)
__device__ __align__(16) __half g_hr2[HD];        // published h*Lr (fp16)
__device__ unsigned g_cnt;                        // monotonic barrier counter

// ------------------------------------------------------------------
// Init: reset counter, publish h0 as fp16 (unused by gru_seq prologue,
// kept for uniformity)
// ------------------------------------------------------------------
__global__ void init_kernel(const float* __restrict__ h0) {
    int i = blockIdx.x * blockDim.x + threadIdx.x;
    if (i < HD) g_h2[i] = __float2half_rn(h0[i]);
    if (i == 0) g_cnt = 0u;
}

// ------------------------------------------------------------------
// Precompute: g_pre[t, m, j] = x[t] @ Wm[0:256, :] + bm   (parallel GEMM)
// ------------------------------------------------------------------
__global__ void __launch_bounds__(256) pre_gemm(
    const float* __restrict__ x,
    const float* __restrict__ Wu, const float* __restrict__ Wr, const float* __restrict__ Wc,
    const float* __restrict__ bu, const float* __restrict__ br, const float* __restrict__ bc)
{
    const int z = blockIdx.z;
    const float* __restrict__ W    = (z == 0) ? Wu : ((z == 1) ? Wr : Wc);
    const float* __restrict__ bias = (z == 0) ? bu : ((z == 1) ? br : bc);

    __shared__ __align__(16) float As[64][16];
    __shared__ __align__(16) float Bs[16][64];

    const int tid = threadIdx.x;
    const int tx = tid & 15;
    const int ty = tid >> 4;
    const int row0 = blockIdx.y * 64;
    const int col0 = blockIdx.x * 64;

    float acc[4][4];
#pragma unroll
    for (int i = 0; i < 4; i++)
#pragma unroll
        for (int j = 0; j < 4; j++) acc[i][j] = 0.f;

    for (int k0 = 0; k0 < XD; k0 += 16) {
#pragma unroll
        for (int l = 0; l < 4; l++) {
            int idx = tid + l * 256;
            int kk = idx & 15, r = idx >> 4;
            As[r][kk] = x[(size_t)(row0 + r) * XD + k0 + kk];
        }
#pragma unroll
        for (int l = 0; l < 4; l++) {
            int idx = tid + l * 256;
            int c = idx & 63, kk = idx >> 6;
            Bs[kk][c] = W[(size_t)(k0 + kk) * HD + col0 + c];
        }
        __syncthreads();
#pragma unroll
        for (int kk = 0; kk < 16; kk++) {
            float a[4];
#pragma unroll
            for (int i = 0; i < 4; i++) a[i] = As[ty * 4 + i][kk];
            float4 b4 = ((const float4*)&Bs[kk][0])[tx];
            float b[4] = {b4.x, b4.y, b4.z, b4.w};
#pragma unroll
            for (int i = 0; i < 4; i++)
#pragma unroll
                for (int j = 0; j < 4; j++)
                    acc[i][j] = fmaf(a[i], b[j], acc[i][j]);
        }
        __syncthreads();
    }

#pragma unroll
    for (int i = 0; i < 4; i++) {
        int t = row0 + ty * 4 + i;
#pragma unroll
        for (int j = 0; j < 4; j++) {
            int c = col0 + tx * 4 + j;
            g_pre[(size_t)t * (3 * HD) + (size_t)z * HD + c] = acc[i][j] + bias[c];
        }
    }
}

// ------------------------------------------------------------------
// Helpers
// ------------------------------------------------------------------
#define BAR_SYNC(id)   asm volatile("bar.sync %0, %1;"   :: "r"(id), "r"(NTH) : "memory")
#define BAR_ARRIVE(id) asm volatile("bar.arrive %0, %1;" :: "r"(id), "r"(NTH) : "memory")

__device__ __forceinline__ float warp_sum(float v) {
#pragma unroll
    for (int o = 16; o; o >>= 1) v += __shfl_xor_sync(0xffffffffu, v, o);
    return v;
}

__device__ __forceinline__ float fsig(float x)   { return 1.f / (1.f + __expf(-x)); }
__device__ __forceinline__ float ftanh_(float x) { return 2.f / (1.f + __expf(-2.f * x)) - 1.f; }

__device__ __forceinline__ void st_cg_u32(void* p, unsigned v) {
    asm volatile("st.global.cg.b32 [%0], %1;" :: "l"(p), "r"(v) : "memory");
}
// Release-arrive on the barrier counter: orders ALL this CTA's prior global
// stores (sequenced below us via bar.sync) before the increment — no fence.
__device__ __forceinline__ void red_add_release(unsigned* p, unsigned v) {
    asm volatile("red.release.gpu.global.add.u32 [%0], %1;" :: "l"(p), "r"(v) : "memory");
}
// Acquire-poll of the counter: orders our subsequent stage loads after the
// observed arrivals — no fence.
__device__ __forceinline__ unsigned ld_acq_u32(const unsigned* p) {
    unsigned v;
    asm volatile("ld.acquire.gpu.global.b32 %0, [%1];" : "=r"(v) : "l"(p) : "memory");
    return v;
}

// Two 2048-long dots: packed int4 weights (LDS.128: 4 rows x 2 cols) x fp32 h.
// Lane covers rows {128k + 4*lane + q, q<4} for k<16.
__device__ __forceinline__ void dot2_q(const int4* __restrict__ wp,
                                       const float2* hreg, int lane,
                                       float& r0, float& r1) {
    float a0 = 0.f, a1 = 0.f, b0 = 0.f, b1 = 0.f;
#pragma unroll
    for (int k = 0; k < 16; k++) {
        int4 wv = wp[k * 32 + lane];
        float2 h01 = hreg[2 * k], h23 = hreg[2 * k + 1];
        float2 xa = __half22float2(*(__half2*)&wv.x);
        float2 xb = __half22float2(*(__half2*)&wv.y);
        float2 xc = __half22float2(*(__half2*)&wv.z);
        float2 xd = __half22float2(*(__half2*)&wv.w);
        a0 = fmaf(xa.x, h01.x, a0); a1 = fmaf(xa.y, h01.y, a1);
        a0 = fmaf(xb.x, h23.x, a0); a1 = fmaf(xb.y, h23.y, a1);
        b0 = fmaf(xc.x, h01.x, b0); b1 = fmaf(xc.y, h01.y, b1);
        b0 = fmaf(xd.x, h23.x, b0); b1 = fmaf(xd.y, h23.y, b1);
    }
    r0 = warp_sum(a0 + a1);
    r1 = warp_sum(b0 + b1);
}

__device__ __forceinline__ float dot_y4(const float4* __restrict__ wy4,
                                        const float2* hreg, int lane) {
    float a0 = 0.f, a1 = 0.f;
#pragma unroll
    for (int k = 0; k < 16; k++) {
        float4 wv = wy4[k * 32 + lane];
        float2 h01 = hreg[2 * k], h23 = hreg[2 * k + 1];
        a0 = fmaf(wv.x, h01.x, a0); a1 = fmaf(wv.y, h01.y, a1);
        a0 = fmaf(wv.z, h23.x, a0); a1 = fmaf(wv.w, h23.y, a1);
    }
    return warp_sum(a0 + a1);
}

// Load staged fp16 vector (smem) into fp32 registers, packed row mapping:
// hreg[2k],hreg[2k+1] = rows 128k+4*lane .. +3.
__device__ __forceinline__ void load_hreg(const __half* buf, int lane, float2* hreg) {
#pragma unroll
    for (int k = 0; k < 16; k++) {
        uint2 v = ((const uint2*)buf)[k * 32 + lane];
        hreg[2 * k]     = __half22float2(*(__half2*)&v.x);
        hreg[2 * k + 1] = __half22float2(*(__half2*)&v.y);
    }
}

// Sync-warp global barrier: release-arrive + acquire-poll (fence-free).
// Single counter, one arriving/polling lane per CTA (R7/R9/R11/R12-proven).
__device__ __forceinline__ void gbar(int lane, unsigned gen) {
    if (lane == 0) {
        red_add_release(&g_cnt, 1u);
        const unsigned tgt = gen * GRID;
        while (ld_acq_u32(&g_cnt) < tgt) { }
    }
    __syncwarp();
}

// ------------------------------------------------------------------
// Persistent sequential kernel: 128 co-resident CTAs (1/SM).
// Warps 0-7 compute; warp 8 runs the global barrier + bulk fp16 staging.
// Named arrive/sync barriers: compute never blocks on arrival-only points.
// ------------------------------------------------------------------
__global__ void __launch_bounds__(NTH, 1) gru_seq(
    const float* __restrict__ h0,
    const float* __restrict__ Wu, const float* __restrict__ Wr, const float* __restrict__ Wc,
    const float* __restrict__ Why, const float* __restrict__ by,
    float* __restrict__ out, int out_size)
{
    extern __shared__ char sm[];
    int4*   wP  = (int4*)sm;                    // packed weights
    float*  wyS = (float*)(sm + WY_OFF);        // y cols as float4 tiles
    __half* hB  = (__half*)(sm + HB_OFF);       // staged h  (fp16)
    __half* hrB = hB + HD;                      // staged hr (fp16)

    const int tid  = threadIdx.x;
    const int lane = tid & 31;
    const int w    = tid >> 5;         // 0..8
    const bool comp = (w < 8);
    const int cta  = blockIdx.x;
    const int colBase = cta * COLS;

    // ---- one-time: pack h-part weights into per-warp int4 tiles ----
#pragma unroll 1
    for (int m = 0; m < 3; m++) {
        const float* __restrict__ Wm =
            ((m == 0) ? Wu : ((m == 1) ? Wr : Wc)) + (size_t)XD * HD;  // skip x rows
        for (int idx = tid; idx < COLS * HD; idx += NTH) {
            int cl  = idx & (COLS - 1);
            int row = idx >> 4;
            int p = cl >> 1, sub = cl & 1;
            int k = row >> 7, ln = (row >> 2) & 31, q = row & 3;
            __half* dst = (__half*)(wP + ((m * 8 + p) * 512 + k * 32 + ln));
            dst[sub * 4 + q] = __float2half_rn(Wm[(size_t)row * HD + colBase + cl]);
        }
    }
    // y columns (float4 tiles): global y cols {2*cta, 2*cta+1}
    for (int idx = tid; idx < 2 * HD; idx += NTH) {
        int c = idx & 1, row = idx >> 1;
        int k = row >> 7, ln = (row >> 2) & 31, q = row & 3;
        wyS[c * HD + (k * 32 + ln) * 4 + q] = Why[(size_t)row * YD + cta * 2 + c];
    }
    // initial h staged as fp16 (row order)
    for (int idx = tid; idx < HD; idx += NTH)
        hB[idx] = __float2half_rn(h0[idx]);

    const int j0 = colBase + (comp ? 2 * w : 0), j1 = j0 + 1;
    const int4* wpU = wP + (size_t)(0 * 8 + (comp ? w : 0)) * 512;
    const int4* wpR = wP + (size_t)(1 * 8 + (comp ? w : 0)) * 512;
    const int4* wpC = wP + (size_t)(2 * 8 + (comp ? w : 0)) * 512;
    const float4* wy4 = (const float4*)(wyS + (w < 2 ? w : 0) * HD);
    const float   yb  = (w < 2) ? by[cta * 2 + w] : 0.f;

    // own-column state kept exact in fp32 registers across steps
    float hold0 = 0.f, hold1 = 0.f;
    float2 pu = make_float2(0.f, 0.f), pr = pu, pc = pu;
    if (comp) {
        hold0 = h0[j0]; hold1 = h0[j1];
        pu = __ldcg((const float2*)&g_pre[0 * HD + j0]);
        pr = __ldcg((const float2*)&g_pre[1 * HD + j0]);
        pc = __ldcg((const float2*)&g_pre[2 * HD + j0]);
    }
    __syncthreads();

    float2 hreg[32];

    for (int t = 0; t < TT; t++) {
        if (comp) {
            // hB holds h_t (fp16) -> registers fp32
            load_hreg(hB, lane, hreg);

            // ---- reset gate, publish h*Lr (fp16) ----
            float r0, r1;
            dot2_q(wpR, hreg, lane, r0, r1);
            r0 = fsig(r0 + pr.x);
            r1 = fsig(r1 + pr.y);
            if (lane == 0) {
                __half2 hv = __floats2half2_rn(hold0 * r0, hold1 * r1);
                st_cg_u32(&g_hr2[j0], *(unsigned*)&hv);
            }
            BAR_ARRIVE(1);                      // hr stores issued; don't block

            // ---- B1 shadow: update gate + y[t-1] ----
            float u0, u1;
            dot2_q(wpU, hreg, lane, u0, u1);
            u0 = fsig(u0 + pu.x);
            u1 = fsig(u1 + pu.y);
            if (w < 2 && t > 0) {
                float yv = dot_y4(wy4, hreg, lane) + yb;
                if (lane == 0) out[(size_t)(t - 1) * YD + cta * 2 + w] = yv;
            }
            BAR_SYNC(2);                        // wait: hr staged into hrB

            // ---- candidate + new h (hreg reused for hr) ----
            load_hreg(hrB, lane, hreg);
            float cc0, cc1;
            dot2_q(wpC, hreg, lane, cc0, cc1);
            cc0 = ftanh_(cc0 + pc.x);
            cc1 = ftanh_(cc1 + pc.y);
            const float hn0 = cc0 * u0 + hold0 * (1.f - u0);
            const float hn1 = cc1 * u1 + hold1 * (1.f - u1);
            hold0 = hn0; hold1 = hn1;           // exact fp32 carry
            if (lane == 0) {
                __half2 hv = __floats2half2_rn(hn0, hn1);
                st_cg_u32(&g_h2[j0], *(unsigned*)&hv);
            }
            BAR_ARRIVE(3);                      // h stores issued; don't block

            // ---- B2 shadow: prefetch pre[t+1] ----
            if (t + 1 < TT) {
                const float* pn = g_pre + (size_t)(t + 1) * (3 * HD);
                pu = __ldcg((const float2*)&pn[0 * HD + j0]);
                pr = __ldcg((const float2*)&pn[1 * HD + j0]);
                pc = __ldcg((const float2*)&pn[2 * HD + j0]);
            }
            BAR_SYNC(4);                        // wait: h_{t+1} staged into hB
        } else {
            // ================= sync warp =================
            BAR_SYNC(1);                        // all compute warps issued hr stores
            gbar(lane, (unsigned)(2 * t + 1));
            {   // bulk stage hr (4KB fp16): 8 LDG.128 batched, then 8 STS.128
                int4 tmp[8];
#pragma unroll
                for (int i = 0; i < 8; i++) tmp[i] = __ldcg((const int4*)g_hr2 + i * 32 + lane);
#pragma unroll
                for (int i = 0; i < 8; i++) ((int4*)hrB)[i * 32 + lane] = tmp[i];
            }
            BAR_ARRIVE(2);                      // hrB ready

            BAR_SYNC(3);                        // all compute warps issued h stores
            gbar(lane, (unsigned)(2 * t + 2));
            {
                int4 tmp[8];
#pragma unroll
                for (int i = 0; i < 8; i++) tmp[i] = __ldcg((const int4*)g_h2 + i * 32 + lane);
#pragma unroll
                for (int i = 0; i < 8; i++) ((int4*)hB)[i * 32 + lane] = tmp[i];
            }
            BAR_ARRIVE(4);                      // hB ready
        }
    }

    // ---- epilogue: hB = h_TT ----
    if (w < 2) {
        load_hreg(hB, lane, hreg);
        float yv = dot_y4(wy4, hreg, lane) + yb;
        if (lane == 0) out[(size_t)(TT - 1) * YD + cta * 2 + w] = yv;
    }
    // h_fin: exact fp32 own-column state
    if (comp && lane == 0 && out_size >= TT * YD + HD) {
        out[(size_t)TT * YD + j0] = hold0;
        out[(size_t)TT * YD + j1] = hold1;
    }
}

// ------------------------------------------------------------------
// Launch
// ------------------------------------------------------------------
extern "C" void kernel_launch(void* const* d_in, const int* in_sizes, int n_in,
                              void* d_out, int out_size) {
    const float* x   = (const float*)d_in[0];
    const float* h0  = (const float*)d_in[1];
    const float* Wc  = (const float*)d_in[2];
    const float* Wu  = (const float*)d_in[3];
    const float* Wr  = (const float*)d_in[4];
    const float* bc  = (const float*)d_in[5];
    const float* bu  = (const float*)d_in[6];
    const float* br  = (const float*)d_in[7];
    const float* Why = (const float*)d_in[8];
    const float* by  = (const float*)d_in[9];
    float* out = (float*)d_out;

    cudaFuncSetAttribute(gru_seq, cudaFuncAttributeMaxDynamicSharedMemorySize, SMEM_SEQ);

    init_kernel<<<8, 256>>>(h0);

    dim3 g(HD / 64, TT / 64, 3);
    pre_gemm<<<g, 256>>>(x, Wu, Wr, Wc, bu, br, bc);

    gru_seq<<<GRID, NTH, SMEM_SEQ>>>(h0, Wu, Wr, Wc, Why, by, out, out_size);
}